// round 7
// baseline (speedup 1.0000x reference)
#include <cuda_runtime.h>
#include <math.h>

// Problem constants
#define SEG      32
#define DD       256          // embedding dim D
#define ROWS     32768        // B*N
#define DIM      257          // Lorentz dim D+1
#define TILE     8            // rows per tile in encode
#define TILES    (ROWS / TILE)   // 4096 tiles per series

__device__ __forceinline__ float wredsum(float v) {
    v += __shfl_xor_sync(0xffffffffu, v, 16);
    v += __shfl_xor_sync(0xffffffffu, v, 8);
    v += __shfl_xor_sync(0xffffffffu, v, 4);
    v += __shfl_xor_sync(0xffffffffu, v, 2);
    v += __shfl_xor_sync(0xffffffffu, v, 1);
    return v;
}

// ---------------- Kernel 1: encode + hyperbolic (proven ~106us form) ----------------
__global__ __launch_bounds__(256, 3)
void encode_hyp_kernel(const float* __restrict__ xt, const float* __restrict__ xc,
                       const float* __restrict__ xf, const float* __restrict__ xr,
                       const float* __restrict__ W0, const float* __restrict__ b0,
                       const float* __restrict__ W1, const float* __restrict__ b1,
                       const float* __restrict__ W2, const float* __restrict__ b2,
                       const float* __restrict__ W3, const float* __restrict__ b3,
                       const float* __restrict__ esp,
                       float* __restrict__ out)
{
    __shared__ float xs[TILE * SEG];     // 256 floats
    __shared__ float zsm[TILE * DD];     // 8 KB

    const int tid = threadIdx.x;
    const int w = tid >> 5;
    const int l = tid & 31;

    const int s      = blockIdx.x & 3;
    const int chunk  = blockIdx.x >> 2;
    const int stride = gridDim.x >> 2;

    const float* Wp = (s == 0) ? W0 : (s == 1) ? W1 : (s == 2) ? W2 : W3;
    const float* bp = (s == 0) ? b0 : (s == 1) ? b1 : (s == 2) ? b2 : b3;
    const float* xp = (s == 0) ? xt : (s == 1) ? xc : (s == 2) ? xf : xr;

    float4 Wreg[8];
    {
        const float4* W4 = (const float4*)(Wp + tid * SEG);
        #pragma unroll
        for (int i = 0; i < 8; i++) Wreg[i] = W4[i];
    }
    const float bias = bp[tid];

    const float ta  = tanhf(*esp);
    const float taa = fabsf(ta);

    int tile = chunk;
    float v = (tile < TILES) ? xp[tile * (TILE * SEG) + tid] : 0.f;

    for (; tile < TILES; tile += stride) {
        __syncthreads();
        xs[tid] = v;
        __syncthreads();

        int nt = tile + stride;
        if (nt < TILES) v = xp[nt * (TILE * SEG) + tid];   // prefetch

        float acc[TILE];
        #pragma unroll
        for (int r = 0; r < TILE; r++) acc[r] = bias;

        #pragma unroll
        for (int i = 0; i < 8; i++) {
            const float4 wv = Wreg[i];
            #pragma unroll
            for (int r = 0; r < TILE; r++) {
                float4 xv = *(const float4*)(xs + r * SEG + i * 4);
                float a = acc[r];
                a = fmaf(wv.x, xv.x, a);
                a = fmaf(wv.y, xv.y, a);
                a = fmaf(wv.z, xv.z, a);
                a = fmaf(wv.w, xv.w, a);
                acc[r] = a;
            }
        }

        #pragma unroll
        for (int r = 0; r < TILE; r++) zsm[r * DD + tid] = acc[r];
        __syncthreads();

        // hyperbolic epilogue: warp w -> row w
        {
            const int r = tile * TILE + w;

            float z[8];
            float lo = 0.f;
            #pragma unroll
            for (int j = 0; j < 8; j++) {
                z[j] = zsm[w * DD + l + 32 * j];
                lo = fmaf(z[j], z[j], lo);
            }
            lo = wredsum(lo);

            float zn = sqrtf(lo);
            float n  = taa * zn;
            float s1 = ta * fminf(n, 1.5f) / fmaxf(n, 1e-8f);
            float nn = fabsf(s1) * zn;
            float ns = fmaxf(nn, 1e-9f);
            float sh = sinhf(nn);
            float F  = s1 * sh / ns;
            float sx = sh * nn / ns;
            float x0v = sqrtf(1.f + sx * sx);

            float* hp = out + (size_t)s * ((size_t)ROWS * DIM) + (size_t)r * DIM;
            #pragma unroll
            for (int j = 0; j < 8; j++) hp[1 + l + 32 * j] = z[j] * F;
            if (l == 0) hp[0] = x0v;
        }
    }
}

// ---------------- Kernel 2: fusion, phase-split with sP in SMEM ----------------
// 16 rows per block-tile. Phase A: warp per 2 rows loads h, computes Gram ->
// SMEM, vectors -> SMEM (registers stay low -> 3 blocks/SM). Phase B: warp 0,
// lane-per-row scalar Karcher (16x warp-instr dedup). Phase C: combined from
// SMEM, streaming stores. Persistent grid, reversed tiles for L2 reuse.
#define RPB    16
#define NT2    (ROWS / RPB)        // 2048
#define RDW    15                  // per-row scalar record stride (odd)
#define SP_F   (RPB * 4 * 256)     // 16384 floats
#define RD_F   (RPB * RDW)
#define GO_F   (RPB * 5)
#define SM2_BYTES ((SP_F + RD_F + GO_F) * 4)

extern __shared__ float fsm[];

__global__ __launch_bounds__(256, 3)
void fusion_kernel(const float* __restrict__ lwp, float* __restrict__ out)
{
    float* spsm   = fsm;                 // [(lr*4+c)*256 + e]
    float* rowdat = fsm + SP_F;          // [lr*15 + k] : gram[10], tP[4]
    float* gout   = rowdat + RD_F;       // [lr*5 + k]  : gam[4], tm

    const int tid = threadIdx.x;
    const int w = tid >> 5;
    const int l = tid & 31;

    float lw0 = lwp[0], lw1 = lwp[1], lw2 = lwp[2], lw3 = lwp[3];
    float mxw = fmaxf(fmaxf(lw0, lw1), fmaxf(lw2, lw3));
    float e0 = expf(lw0 - mxw), e1 = expf(lw1 - mxw);
    float e2 = expf(lw2 - mxw), e3 = expf(lw3 - mxw);
    float esum = e0 + e1 + e2 + e3;
    float wgt[4] = {e0 / esum, e1 / esum, e2 / esum, e3 / esum};

    for (int ti = blockIdx.x; ti < NT2; ti += gridDim.x) {
        const int tilerow = (NT2 - 1 - ti) * RPB;   // reversed: L2-hot first
        __syncthreads();   // spsm/gout free from previous iteration

        // ---- Phase A: warp w owns local rows 2w, 2w+1 (sequential, low regs) ----
        #pragma unroll
        for (int t = 0; t < 2; t++) {
            const int lr = 2 * w + t;
            const int r  = tilerow + lr;

            float sP[4][8], tPl[4];
            #pragma unroll
            for (int c = 0; c < 4; c++) {
                const float* hp = out + (size_t)c * ((size_t)ROWS * DIM) + (size_t)r * DIM;
                tPl[c] = __ldg(hp);
                #pragma unroll
                for (int j = 0; j < 8; j++) sP[c][j] = __ldg(hp + 1 + l + 32 * j);
            }

            float pr[10];
            {
                int idx = 0;
                #pragma unroll
                for (int c = 0; c < 4; c++)
                    #pragma unroll
                    for (int d = c; d < 4; d++) {
                        float lo = 0.f;
                        #pragma unroll
                        for (int j = 0; j < 8; j++) lo = fmaf(sP[c][j], sP[d][j], lo);
                        pr[idx++] = lo;
                    }
            }
            #pragma unroll
            for (int i = 0; i < 10; i++) pr[i] = wredsum(pr[i]);

            // stash vectors + scalars
            #pragma unroll
            for (int c = 0; c < 4; c++)
                #pragma unroll
                for (int j = 0; j < 8; j++)
                    spsm[(lr * 4 + c) * 256 + l + 32 * j] = sP[c][j];
            if (l == 0) {
                #pragma unroll
                for (int i = 0; i < 10; i++) rowdat[lr * RDW + i] = pr[i];
                #pragma unroll
                for (int c = 0; c < 4; c++) rowdat[lr * RDW + 10 + c] = tPl[c];
            }
        }
        __syncthreads();

        // ---- Phase B: scalar Karcher chain, lane-per-row in warp 0 ----
        if (w == 0) {
            const int row = l & 15;

            float P[4][4], tP[4];
            {
                int idx = 0;
                #pragma unroll
                for (int c = 0; c < 4; c++)
                    #pragma unroll
                    for (int d = c; d < 4; d++) {
                        float vv = rowdat[row * RDW + idx];
                        P[c][d] = vv; P[d][c] = vv; idx++;
                    }
                #pragma unroll
                for (int c = 0; c < 4; c++) tP[c] = rowdat[row * RDW + 10 + c];
            }
            float S[4];
            #pragma unroll
            for (int c = 0; c < 4; c++) S[c] = P[c][c];

            float gam[4];
            float wt_t = 0.f;
            #pragma unroll
            for (int c = 0; c < 4; c++) {
                float alpha = fmaxf(tP[c], 1.0f + 1e-7f);
                float dist  = acoshf(alpha);
                float ut    = tP[c] - alpha;
                float un2   = fmaxf(S[c] - ut * ut, 1e-12f);
                float g     = dist / sqrtf(un2);
                float wg    = wgt[c] * g;
                gam[c] = wg;
                wt_t   = fmaf(wg, ut, wt_t);
            }
            float wtsp2;
            {
                float t = 0.f;
                #pragma unroll
                for (int c = 0; c < 4; c++) {
                    float u = 0.f;
                    #pragma unroll
                    for (int d = 0; d < 4; d++) u = fmaf(gam[d], P[c][d], u);
                    t = fmaf(gam[c], u, t);
                }
                wtsp2 = fmaxf(t, 0.f);
            }
            float Ssm, tm;
            {
                float nrm = sqrtf(wtsp2 + wt_t * wt_t);
                float cs  = fminf(nrm, 2.0f) / fmaxf(nrm, 1e-12f);
                float S2  = cs * cs * wtsp2;
                float nn  = sqrtf(S2);
                float ns  = fmaxf(nn, 1e-9f);
                float sh  = sinhf(nn);
                float fac = cs * sh / ns;
                #pragma unroll
                for (int c = 0; c < 4; c++) gam[c] *= fac;
                float sx = sh * nn / ns;
                Ssm = sx * sx;
                tm  = sqrtf(1.f + Ssm);
            }

            #pragma unroll
            for (int it = 0; it < 5; it++) {
                float dl[4];
                #pragma unroll
                for (int c = 0; c < 4; c++) {
                    float t = 0.f;
                    #pragma unroll
                    for (int d = 0; d < 4; d++) t = fmaf(gam[d], P[d][c], t);
                    dl[c] = t;
                }
                float wgv[4], utv[4];
                float A = 0.f, wv_t = 0.f;
                #pragma unroll
                for (int c = 0; c < 4; c++) {
                    float alpha = fmaxf(tm * tP[c] - dl[c], 1.0f + 1e-7f);
                    float dist  = acoshf(alpha);
                    float ut    = tP[c] - alpha * tm;
                    float U2sp  = S[c] - 2.f * alpha * dl[c] + alpha * alpha * Ssm;
                    float un2   = fmaxf(U2sp - ut * ut, 1e-12f);
                    float g     = dist / sqrtf(un2);
                    float wg    = wgt[c] * g;
                    wgv[c] = wg; utv[c] = ut;
                    A    = fmaf(wg, alpha, A);
                    wv_t = fmaf(wg, ut, wv_t);
                }
                float wvg[4];
                #pragma unroll
                for (int c = 0; c < 4; c++) wvg[c] = wgv[c] - A * gam[c];

                float wvsp2;
                {
                    float t = 0.f;
                    #pragma unroll
                    for (int c = 0; c < 4; c++) {
                        float u = 0.f;
                        #pragma unroll
                        for (int d = 0; d < 4; d++) u = fmaf(wvg[d], P[c][d], u);
                        t = fmaf(wvg[c], u, t);
                    }
                    wvsp2 = fmaxf(t, 0.f);
                }

                float nrm = sqrtf(wvsp2 + wv_t * wv_t);
                float cs  = fminf(nrm, 2.0f) / fmaxf(nrm, 1e-12f);
                float q   = 0.1f * cs;
                float mk  = fmaxf(q * q * (wvsp2 - wv_t * wv_t), 1e-12f);
                float th  = sqrtf(mk);
                float ch  = coshf(th);
                float shh = sinhf(th);
                float cq  = shh * q / th;

                #pragma unroll
                for (int c = 0; c < 4; c++) gam[c] = fmaf(cq, wvg[c], ch * gam[c]);

                {
                    float t = 0.f;
                    #pragma unroll
                    for (int c = 0; c < 4; c++) {
                        float u = 0.f;
                        #pragma unroll
                        for (int d = 0; d < 4; d++) u = fmaf(gam[d], P[c][d], u);
                        t = fmaf(gam[c], u, t);
                    }
                    Ssm = fmaxf(t, 0.f);
                }
                tm = sqrtf(1.f + Ssm);
            }

            if (l < 16) {
                #pragma unroll
                for (int c = 0; c < 4; c++) gout[row * 5 + c] = gam[c];
                gout[row * 5 + 4] = tm;
            }
        }
        __syncthreads();

        // ---- Phase C: combined from SMEM, streaming stores ----
        #pragma unroll
        for (int t = 0; t < 2; t++) {
            const int lr = 2 * w + t;
            const int r  = tilerow + lr;

            float g0 = gout[lr * 5 + 0], g1 = gout[lr * 5 + 1];
            float g2 = gout[lr * 5 + 2], g3 = gout[lr * 5 + 3];
            float tm = gout[lr * 5 + 4];

            float* cp = out + 4 * ((size_t)ROWS * DIM) + (size_t)r * DIM;
            #pragma unroll
            for (int j = 0; j < 8; j++) {
                int e = l + 32 * j;
                float vv = g0 * spsm[(lr * 4 + 0) * 256 + e];
                vv = fmaf(g1, spsm[(lr * 4 + 1) * 256 + e], vv);
                vv = fmaf(g2, spsm[(lr * 4 + 2) * 256 + e], vv);
                vv = fmaf(g3, spsm[(lr * 4 + 3) * 256 + e], vv);
                __stcs(cp + 1 + e, vv);
            }
            if (l == 0) __stcs(cp, tm);
        }
    }
}

extern "C" void kernel_launch(void* const* d_in, const int* in_sizes, int n_in,
                              void* d_out, int out_size) {
    (void)in_sizes; (void)n_in; (void)out_size;
    const float* xt = (const float*)d_in[0];
    const float* xc = (const float*)d_in[1];
    const float* xf = (const float*)d_in[2];
    const float* xr = (const float*)d_in[3];
    const float* W0 = (const float*)d_in[4];
    const float* b0 = (const float*)d_in[5];
    const float* W1 = (const float*)d_in[6];
    const float* b1 = (const float*)d_in[7];
    const float* W2 = (const float*)d_in[8];
    const float* b2 = (const float*)d_in[9];
    const float* W3 = (const float*)d_in[10];
    const float* b3 = (const float*)d_in[11];
    const float* es = (const float*)d_in[12];
    const float* lw = (const float*)d_in[13];
    float* out = (float*)d_out;

    int nsm = 148;
    cudaDeviceGetAttribute(&nsm, cudaDevAttrMultiProcessorCount, 0);
    if (nsm <= 0) nsm = 148;

    encode_hyp_kernel<<<12 * nsm, 256>>>(xt, xc, xf, xr,
                                         W0, b0, W1, b1, W2, b2, W3, b3,
                                         es, out);

    cudaFuncSetAttribute(fusion_kernel,
                         cudaFuncAttributeMaxDynamicSharedMemorySize, SM2_BYTES);
    fusion_kernel<<<3 * nsm, 256, SM2_BYTES>>>(lw, out);
}

// round 8
// speedup vs baseline: 1.5032x; 1.5032x over previous
#include <cuda_runtime.h>
#include <math.h>

// Problem constants
#define SEG      32
#define DD       256          // embedding dim D
#define ROWS     32768        // B*N
#define DIM      257          // Lorentz dim D+1
#define TILE     8            // rows per tile in encode
#define TILES    (ROWS / TILE)   // 4096 tiles per series

// ---------------- packed f32x2 helpers ----------------
typedef struct __align__(16) { unsigned long long a, b; } u64x2;

__device__ __forceinline__ unsigned long long pack2(float lo, float hi) {
    unsigned long long r;
    asm("mov.b64 %0, {%1, %2};" : "=l"(r) : "f"(lo), "f"(hi));
    return r;
}
__device__ __forceinline__ void unpack2(unsigned long long v, float& lo, float& hi) {
    asm("mov.b64 {%0, %1}, %2;" : "=f"(lo), "=f"(hi) : "l"(v));
}
__device__ __forceinline__ void ffma2(unsigned long long& d,
                                      unsigned long long a, unsigned long long b) {
    asm("fma.rn.f32x2 %0, %1, %2, %0;" : "+l"(d) : "l"(a), "l"(b));
}

__device__ __forceinline__ float wredsum(float v) {
    v += __shfl_xor_sync(0xffffffffu, v, 16);
    v += __shfl_xor_sync(0xffffffffu, v, 8);
    v += __shfl_xor_sync(0xffffffffu, v, 4);
    v += __shfl_xor_sync(0xffffffffu, v, 2);
    v += __shfl_xor_sync(0xffffffffu, v, 1);
    return v;
}

// ---------------- Kernel 1: encode + hyperbolic ----------------
// k-pair-outer / row-inner loop: 8 independent f32x2 accumulator chains
// (no dependency stalls) + packed FMA (half the FMA issue ops of scalar).
__global__ __launch_bounds__(256, 3)
void encode_hyp_kernel(const float* __restrict__ xt, const float* __restrict__ xc,
                       const float* __restrict__ xf, const float* __restrict__ xr,
                       const float* __restrict__ W0, const float* __restrict__ b0,
                       const float* __restrict__ W1, const float* __restrict__ b1,
                       const float* __restrict__ W2, const float* __restrict__ b2,
                       const float* __restrict__ W3, const float* __restrict__ b3,
                       const float* __restrict__ esp,
                       float* __restrict__ out)
{
    __shared__ float xs[TILE * SEG];     // 256 floats
    __shared__ float zsm[TILE * DD];     // 8 KB

    const int tid = threadIdx.x;
    const int w = tid >> 5;
    const int l = tid & 31;

    const int s      = blockIdx.x & 3;
    const int chunk  = blockIdx.x >> 2;
    const int stride = gridDim.x >> 2;

    const float* Wp = (s == 0) ? W0 : (s == 1) ? W1 : (s == 2) ? W2 : W3;
    const float* bp = (s == 0) ? b0 : (s == 1) ? b1 : (s == 2) ? b2 : b3;
    const float* xp = (s == 0) ? xt : (s == 1) ? xc : (s == 2) ? xf : xr;

    // W row for d = tid as 16 packed f32x2 (pair p = k{2p,2p+1})
    unsigned long long wp[16];
    {
        const u64x2* W16 = (const u64x2*)(Wp + tid * SEG);
        #pragma unroll
        for (int i = 0; i < 8; i++) {
            u64x2 v = W16[i];
            wp[2 * i]     = v.a;
            wp[2 * i + 1] = v.b;
        }
    }
    const float bias = bp[tid];

    const float ta  = tanhf(*esp);
    const float taa = fabsf(ta);

    int tile = chunk;
    float v = (tile < TILES) ? xp[tile * (TILE * SEG) + tid] : 0.f;

    for (; tile < TILES; tile += stride) {
        __syncthreads();
        xs[tid] = v;
        __syncthreads();

        int nt = tile + stride;
        if (nt < TILES) v = xp[nt * (TILE * SEG) + tid];   // prefetch

        // encode: 8 interleaved f32x2 accumulator chains
        unsigned long long acc[TILE];
        #pragma unroll
        for (int r = 0; r < TILE; r++) acc[r] = pack2(bias, 0.f);

        #pragma unroll
        for (int i = 0; i < 8; i++) {          // 4-float chunk of k
            const unsigned long long wa = wp[2 * i];
            const unsigned long long wb = wp[2 * i + 1];
            #pragma unroll
            for (int r = 0; r < TILE; r++) {
                u64x2 xv = *(const u64x2*)(xs + r * SEG + i * 4);  // LDS.128 bcast
                ffma2(acc[r], wa, xv.a);
                ffma2(acc[r], wb, xv.b);
            }
        }

        #pragma unroll
        for (int r = 0; r < TILE; r++) {
            float lo, hi;
            unpack2(acc[r], lo, hi);
            zsm[r * DD + tid] = lo + hi;
        }
        __syncthreads();

        // hyperbolic epilogue: warp w -> row w
        {
            const int r = tile * TILE + w;

            float z[8];
            float lo = 0.f;
            #pragma unroll
            for (int j = 0; j < 8; j++) {
                z[j] = zsm[w * DD + l + 32 * j];
                lo = fmaf(z[j], z[j], lo);
            }
            lo = wredsum(lo);

            float zn = sqrtf(lo);
            float n  = taa * zn;
            float s1 = ta * fminf(n, 1.5f) / fmaxf(n, 1e-8f);
            float nn = fabsf(s1) * zn;
            float ns = fmaxf(nn, 1e-9f);
            float sh = sinhf(nn);
            float F  = s1 * sh / ns;
            float sx = sh * nn / ns;
            float x0v = sqrtf(1.f + sx * sx);

            float* hp = out + (size_t)s * ((size_t)ROWS * DIM) + (size_t)r * DIM;
            #pragma unroll
            for (int j = 0; j < 8; j++) hp[1 + l + 32 * j] = z[j] * F;
            if (l == 0) hp[0] = x0v;
        }
    }
}

// ---------------- Kernel 2: fusion (exact R3 config, 66us) ----------------
// Block = 16 rows. Phase A: warp per 2 rows computes Gram + tP -> SMEM, sP in
// registers. Phase B: one warp, lane-per-row scalar Karcher (16x dedup).
// Phase C: combined from register-resident sP (streaming stores).
#define RPB 16
#define GSTRIDE 17

__global__ __launch_bounds__(256, 2)
void fusion_kernel(const float* __restrict__ lwp, float* __restrict__ out)
{
    __shared__ float gramsm[RPB * GSTRIDE];   // per row: P[10], tP[4]
    __shared__ float gout[RPB * 8];           // per row: gam[4], tm

    const int tid = threadIdx.x;
    const int w = tid >> 5;
    const int l = tid & 31;

    float lw0 = lwp[0], lw1 = lwp[1], lw2 = lwp[2], lw3 = lwp[3];
    float mxw = fmaxf(fmaxf(lw0, lw1), fmaxf(lw2, lw3));
    float e0 = expf(lw0 - mxw), e1 = expf(lw1 - mxw);
    float e2 = expf(lw2 - mxw), e3 = expf(lw3 - mxw);
    float esum = e0 + e1 + e2 + e3;
    float wgt[4] = {e0 / esum, e1 / esum, e2 / esum, e3 / esum};

    // -------- Phase A: Gram matrices, warp w owns local rows 2w, 2w+1 --------
    float sP[2][4][8];
    #pragma unroll
    for (int t = 0; t < 2; t++) {
        const int lr = 2 * w + t;
        const int r  = blockIdx.x * RPB + lr;

        float tPl[4];
        #pragma unroll
        for (int c = 0; c < 4; c++) {
            const float* hp = out + (size_t)c * ((size_t)ROWS * DIM) + (size_t)r * DIM;
            tPl[c] = hp[0];
            #pragma unroll
            for (int j = 0; j < 8; j++) sP[t][c][j] = hp[1 + l + 32 * j];
        }

        float pr[10];
        {
            int idx = 0;
            #pragma unroll
            for (int c = 0; c < 4; c++)
                #pragma unroll
                for (int d = c; d < 4; d++) {
                    float lo = 0.f;
                    #pragma unroll
                    for (int j = 0; j < 8; j++) lo = fmaf(sP[t][c][j], sP[t][d][j], lo);
                    pr[idx++] = lo;
                }
        }
        #pragma unroll
        for (int i = 0; i < 10; i++) pr[i] = wredsum(pr[i]);

        if (l == 0) {
            #pragma unroll
            for (int i = 0; i < 10; i++) gramsm[lr * GSTRIDE + i] = pr[i];
            #pragma unroll
            for (int c = 0; c < 4; c++) gramsm[lr * GSTRIDE + 10 + c] = tPl[c];
        }
    }
    __syncthreads();

    // -------- Phase B: scalar Karcher recurrence, lane-per-row in warp 0 --------
    if (w == 0) {
        const int row = l & 15;

        float P[4][4], tP[4];
        {
            int idx = 0;
            #pragma unroll
            for (int c = 0; c < 4; c++)
                #pragma unroll
                for (int d = c; d < 4; d++) {
                    float vv = gramsm[row * GSTRIDE + idx];
                    P[c][d] = vv; P[d][c] = vv;
                    idx++;
                }
            #pragma unroll
            for (int c = 0; c < 4; c++) tP[c] = gramsm[row * GSTRIDE + 10 + c];
        }
        float S[4];
        #pragma unroll
        for (int c = 0; c < 4; c++) S[c] = P[c][c];

        float gam[4];
        float wt_t = 0.f;
        #pragma unroll
        for (int c = 0; c < 4; c++) {
            float alpha = fmaxf(tP[c], 1.0f + 1e-7f);
            float dist  = acoshf(alpha);
            float ut    = tP[c] - alpha;
            float un2   = fmaxf(S[c] - ut * ut, 1e-12f);
            float g     = dist / sqrtf(un2);
            float wg    = wgt[c] * g;
            gam[c] = wg;
            wt_t   = fmaf(wg, ut, wt_t);
        }
        float wtsp2;
        {
            float t = 0.f;
            #pragma unroll
            for (int c = 0; c < 4; c++) {
                float u = 0.f;
                #pragma unroll
                for (int d = 0; d < 4; d++) u = fmaf(gam[d], P[c][d], u);
                t = fmaf(gam[c], u, t);
            }
            wtsp2 = fmaxf(t, 0.f);
        }
        float Ssm, tm;
        {
            float nrm = sqrtf(wtsp2 + wt_t * wt_t);
            float cs  = fminf(nrm, 2.0f) / fmaxf(nrm, 1e-12f);
            float S2  = cs * cs * wtsp2;
            float nn  = sqrtf(S2);
            float ns  = fmaxf(nn, 1e-9f);
            float sh  = sinhf(nn);
            float fac = cs * sh / ns;
            #pragma unroll
            for (int c = 0; c < 4; c++) gam[c] *= fac;
            float sx = sh * nn / ns;
            Ssm = sx * sx;
            tm  = sqrtf(1.f + Ssm);
        }

        #pragma unroll
        for (int it = 0; it < 5; it++) {
            float dl[4];
            #pragma unroll
            for (int c = 0; c < 4; c++) {
                float t = 0.f;
                #pragma unroll
                for (int d = 0; d < 4; d++) t = fmaf(gam[d], P[d][c], t);
                dl[c] = t;
            }
            float wgv[4];
            float A = 0.f, wv_t = 0.f;
            #pragma unroll
            for (int c = 0; c < 4; c++) {
                float alpha = fmaxf(tm * tP[c] - dl[c], 1.0f + 1e-7f);
                float dist  = acoshf(alpha);
                float ut    = tP[c] - alpha * tm;
                float U2sp  = S[c] - 2.f * alpha * dl[c] + alpha * alpha * Ssm;
                float un2   = fmaxf(U2sp - ut * ut, 1e-12f);
                float g     = dist / sqrtf(un2);
                float wg    = wgt[c] * g;
                wgv[c] = wg;
                A    = fmaf(wg, alpha, A);
                wv_t = fmaf(wg, ut, wv_t);
            }
            float wvg[4];
            #pragma unroll
            for (int c = 0; c < 4; c++) wvg[c] = wgv[c] - A * gam[c];

            float wvsp2;
            {
                float t = 0.f;
                #pragma unroll
                for (int c = 0; c < 4; c++) {
                    float u = 0.f;
                    #pragma unroll
                    for (int d = 0; d < 4; d++) u = fmaf(wvg[d], P[c][d], u);
                    t = fmaf(wvg[c], u, t);
                }
                wvsp2 = fmaxf(t, 0.f);
            }

            float nrm = sqrtf(wvsp2 + wv_t * wv_t);
            float cs  = fminf(nrm, 2.0f) / fmaxf(nrm, 1e-12f);
            float q   = 0.1f * cs;
            float mk  = fmaxf(q * q * (wvsp2 - wv_t * wv_t), 1e-12f);
            float th  = sqrtf(mk);
            float ch  = coshf(th);
            float shh = sinhf(th);
            float cq  = shh * q / th;

            #pragma unroll
            for (int c = 0; c < 4; c++) gam[c] = fmaf(cq, wvg[c], ch * gam[c]);

            {
                float t = 0.f;
                #pragma unroll
                for (int c = 0; c < 4; c++) {
                    float u = 0.f;
                    #pragma unroll
                    for (int d = 0; d < 4; d++) u = fmaf(gam[d], P[c][d], u);
                    t = fmaf(gam[c], u, t);
                }
                Ssm = fmaxf(t, 0.f);
            }
            tm = sqrtf(1.f + Ssm);
        }

        if (l < 16) {
            #pragma unroll
            for (int c = 0; c < 4; c++) gout[row * 8 + c] = gam[c];
            gout[row * 8 + 4] = tm;
        }
    }
    __syncthreads();

    // -------- Phase C: write combined from register-resident sP --------
    #pragma unroll
    for (int t = 0; t < 2; t++) {
        const int lr = 2 * w + t;
        const int r  = blockIdx.x * RPB + lr;

        float g0 = gout[lr * 8 + 0], g1 = gout[lr * 8 + 1];
        float g2 = gout[lr * 8 + 2], g3 = gout[lr * 8 + 3];
        float tm = gout[lr * 8 + 4];

        float* cp = out + 4 * ((size_t)ROWS * DIM) + (size_t)r * DIM;
        #pragma unroll
        for (int j = 0; j < 8; j++) {
            float vv = g0 * sP[t][0][j];
            vv = fmaf(g1, sP[t][1][j], vv);
            vv = fmaf(g2, sP[t][2][j], vv);
            vv = fmaf(g3, sP[t][3][j], vv);
            __stcs(cp + 1 + l + 32 * j, vv);
        }
        if (l == 0) __stcs(cp, tm);
    }
}

extern "C" void kernel_launch(void* const* d_in, const int* in_sizes, int n_in,
                              void* d_out, int out_size) {
    (void)in_sizes; (void)n_in; (void)out_size;
    const float* xt = (const float*)d_in[0];
    const float* xc = (const float*)d_in[1];
    const float* xf = (const float*)d_in[2];
    const float* xr = (const float*)d_in[3];
    const float* W0 = (const float*)d_in[4];
    const float* b0 = (const float*)d_in[5];
    const float* W1 = (const float*)d_in[6];
    const float* b1 = (const float*)d_in[7];
    const float* W2 = (const float*)d_in[8];
    const float* b2 = (const float*)d_in[9];
    const float* W3 = (const float*)d_in[10];
    const float* b3 = (const float*)d_in[11];
    const float* es = (const float*)d_in[12];
    const float* lw = (const float*)d_in[13];
    float* out = (float*)d_out;

    int nsm = 148;
    cudaDeviceGetAttribute(&nsm, cudaDevAttrMultiProcessorCount, 0);
    if (nsm <= 0) nsm = 148;

    encode_hyp_kernel<<<12 * nsm, 256>>>(xt, xc, xf, xr,
                                         W0, b0, W1, b1, W2, b2, W3, b3,
                                         es, out);
    fusion_kernel<<<ROWS / RPB, 256>>>(lw, out);
}

// round 9
// speedup vs baseline: 1.6227x; 1.0795x over previous
#include <cuda_runtime.h>
#include <math.h>

// Problem constants
#define SEG      32
#define DD       256          // embedding dim D
#define ROWS     32768        // B*N
#define DIM      257          // Lorentz dim D+1
#define TILE     8            // rows per tile in encode
#define TILES    (ROWS / TILE)   // 4096 tiles per series

// ---------------- packed f32x2 helpers ----------------
typedef struct __align__(16) { unsigned long long a, b; } u64x2;

__device__ __forceinline__ unsigned long long pack2(float lo, float hi) {
    unsigned long long r;
    asm("mov.b64 %0, {%1, %2};" : "=l"(r) : "f"(lo), "f"(hi));
    return r;
}
__device__ __forceinline__ void unpack2(unsigned long long v, float& lo, float& hi) {
    asm("mov.b64 {%0, %1}, %2;" : "=f"(lo), "=f"(hi) : "l"(v));
}
__device__ __forceinline__ void ffma2(unsigned long long& d,
                                      unsigned long long a, unsigned long long b) {
    asm("fma.rn.f32x2 %0, %1, %2, %0;" : "+l"(d) : "l"(a), "l"(b));
}

__device__ __forceinline__ float wredsum(float v) {
    v += __shfl_xor_sync(0xffffffffu, v, 16);
    v += __shfl_xor_sync(0xffffffffu, v, 8);
    v += __shfl_xor_sync(0xffffffffu, v, 4);
    v += __shfl_xor_sync(0xffffffffu, v, 2);
    v += __shfl_xor_sync(0xffffffffu, v, 1);
    return v;
}

// ---------------- Kernel 1: encode + hyperbolic (best known, ~103us) ----------------
__global__ __launch_bounds__(256, 3)
void encode_hyp_kernel(const float* __restrict__ xt, const float* __restrict__ xc,
                       const float* __restrict__ xf, const float* __restrict__ xr,
                       const float* __restrict__ W0, const float* __restrict__ b0,
                       const float* __restrict__ W1, const float* __restrict__ b1,
                       const float* __restrict__ W2, const float* __restrict__ b2,
                       const float* __restrict__ W3, const float* __restrict__ b3,
                       const float* __restrict__ esp,
                       float* __restrict__ out)
{
    __shared__ float xs[TILE * SEG];     // 256 floats
    __shared__ float zsm[TILE * DD];     // 8 KB

    const int tid = threadIdx.x;
    const int w = tid >> 5;
    const int l = tid & 31;

    const int s      = blockIdx.x & 3;
    const int chunk  = blockIdx.x >> 2;
    const int stride = gridDim.x >> 2;

    const float* Wp = (s == 0) ? W0 : (s == 1) ? W1 : (s == 2) ? W2 : W3;
    const float* bp = (s == 0) ? b0 : (s == 1) ? b1 : (s == 2) ? b2 : b3;
    const float* xp = (s == 0) ? xt : (s == 1) ? xc : (s == 2) ? xf : xr;

    unsigned long long wp[16];
    {
        const u64x2* W16 = (const u64x2*)(Wp + tid * SEG);
        #pragma unroll
        for (int i = 0; i < 8; i++) {
            u64x2 v = W16[i];
            wp[2 * i]     = v.a;
            wp[2 * i + 1] = v.b;
        }
    }
    const float bias = bp[tid];

    const float ta  = tanhf(*esp);
    const float taa = fabsf(ta);

    int tile = chunk;
    float v = (tile < TILES) ? xp[tile * (TILE * SEG) + tid] : 0.f;

    for (; tile < TILES; tile += stride) {
        __syncthreads();
        xs[tid] = v;
        __syncthreads();

        int nt = tile + stride;
        if (nt < TILES) v = xp[nt * (TILE * SEG) + tid];   // prefetch

        unsigned long long acc[TILE];
        #pragma unroll
        for (int r = 0; r < TILE; r++) acc[r] = pack2(bias, 0.f);

        #pragma unroll
        for (int i = 0; i < 8; i++) {
            const unsigned long long wa = wp[2 * i];
            const unsigned long long wb = wp[2 * i + 1];
            #pragma unroll
            for (int r = 0; r < TILE; r++) {
                u64x2 xv = *(const u64x2*)(xs + r * SEG + i * 4);  // LDS.128 bcast
                ffma2(acc[r], wa, xv.a);
                ffma2(acc[r], wb, xv.b);
            }
        }

        #pragma unroll
        for (int r = 0; r < TILE; r++) {
            float lo, hi;
            unpack2(acc[r], lo, hi);
            zsm[r * DD + tid] = lo + hi;
        }
        __syncthreads();

        // hyperbolic epilogue: warp w -> row w
        {
            const int r = tile * TILE + w;

            float z[8];
            float lo = 0.f;
            #pragma unroll
            for (int j = 0; j < 8; j++) {
                z[j] = zsm[w * DD + l + 32 * j];
                lo = fmaf(z[j], z[j], lo);
            }
            lo = wredsum(lo);

            float zn = sqrtf(lo);
            float n  = taa * zn;
            float s1 = ta * fminf(n, 1.5f) / fmaxf(n, 1e-8f);
            float nn = fabsf(s1) * zn;
            float ns = fmaxf(nn, 1e-9f);
            float sh = sinhf(nn);
            float F  = s1 * sh / ns;
            float sx = sh * nn / ns;
            float x0v = sqrtf(1.f + sx * sx);

            float* hp = out + (size_t)s * ((size_t)ROWS * DIM) + (size_t)r * DIM;
            #pragma unroll
            for (int j = 0; j < 8; j++) hp[1 + l + 32 * j] = z[j] * F;
            if (l == 0) hp[0] = x0v;
        }
    }
}

// ---------------- Kernel 2: fusion, low-register / L1-reload variant ----------------
// Phase A: warp per 2 rows, load h, Gram -> SMEM, DISCARD vectors (no sP regs).
// Phase B: one warp, lane-per-row scalar Karcher (16x dedup).
// Phase C: re-load h (L1 hits: same lines this block just read), combine, store.
#define RPB 16
#define GSTRIDE 17

__global__ __launch_bounds__(256, 4)
void fusion_kernel(const float* __restrict__ lwp, float* __restrict__ out)
{
    __shared__ float gramsm[RPB * GSTRIDE];   // per row: P[10], tP[4]
    __shared__ float gout[RPB * 8];           // per row: gam[4], tm

    const int tid = threadIdx.x;
    const int w = tid >> 5;
    const int l = tid & 31;

    float lw0 = lwp[0], lw1 = lwp[1], lw2 = lwp[2], lw3 = lwp[3];
    float mxw = fmaxf(fmaxf(lw0, lw1), fmaxf(lw2, lw3));
    float e0 = expf(lw0 - mxw), e1 = expf(lw1 - mxw);
    float e2 = expf(lw2 - mxw), e3 = expf(lw3 - mxw);
    float esum = e0 + e1 + e2 + e3;
    float wgt[4] = {e0 / esum, e1 / esum, e2 / esum, e3 / esum};

    // -------- Phase A: Gram matrices; vectors are NOT kept in registers --------
    #pragma unroll
    for (int t = 0; t < 2; t++) {
        const int lr = 2 * w + t;
        const int r  = blockIdx.x * RPB + lr;

        float sP[4][8], tPl[4];
        #pragma unroll
        for (int c = 0; c < 4; c++) {
            const float* hp = out + (size_t)c * ((size_t)ROWS * DIM) + (size_t)r * DIM;
            tPl[c] = hp[0];
            #pragma unroll
            for (int j = 0; j < 8; j++) sP[c][j] = hp[1 + l + 32 * j];
        }

        float pr[10];
        {
            int idx = 0;
            #pragma unroll
            for (int c = 0; c < 4; c++)
                #pragma unroll
                for (int d = c; d < 4; d++) {
                    float lo = 0.f;
                    #pragma unroll
                    for (int j = 0; j < 8; j++) lo = fmaf(sP[c][j], sP[d][j], lo);
                    pr[idx++] = lo;
                }
        }
        #pragma unroll
        for (int i = 0; i < 10; i++) pr[i] = wredsum(pr[i]);

        if (l == 0) {
            #pragma unroll
            for (int i = 0; i < 10; i++) gramsm[lr * GSTRIDE + i] = pr[i];
            #pragma unroll
            for (int c = 0; c < 4; c++) gramsm[lr * GSTRIDE + 10 + c] = tPl[c];
        }
    }
    __syncthreads();

    // -------- Phase B: scalar Karcher recurrence, lane-per-row in warp 0 --------
    if (w == 0) {
        const int row = l & 15;

        float P[4][4], tP[4];
        {
            int idx = 0;
            #pragma unroll
            for (int c = 0; c < 4; c++)
                #pragma unroll
                for (int d = c; d < 4; d++) {
                    float vv = gramsm[row * GSTRIDE + idx];
                    P[c][d] = vv; P[d][c] = vv;
                    idx++;
                }
            #pragma unroll
            for (int c = 0; c < 4; c++) tP[c] = gramsm[row * GSTRIDE + 10 + c];
        }
        float S[4];
        #pragma unroll
        for (int c = 0; c < 4; c++) S[c] = P[c][c];

        float gam[4];
        float wt_t = 0.f;
        #pragma unroll
        for (int c = 0; c < 4; c++) {
            float alpha = fmaxf(tP[c], 1.0f + 1e-7f);
            float dist  = acoshf(alpha);
            float ut    = tP[c] - alpha;
            float un2   = fmaxf(S[c] - ut * ut, 1e-12f);
            float g     = dist / sqrtf(un2);
            float wg    = wgt[c] * g;
            gam[c] = wg;
            wt_t   = fmaf(wg, ut, wt_t);
        }
        float wtsp2;
        {
            float t = 0.f;
            #pragma unroll
            for (int c = 0; c < 4; c++) {
                float u = 0.f;
                #pragma unroll
                for (int d = 0; d < 4; d++) u = fmaf(gam[d], P[c][d], u);
                t = fmaf(gam[c], u, t);
            }
            wtsp2 = fmaxf(t, 0.f);
        }
        float Ssm, tm;
        {
            float nrm = sqrtf(wtsp2 + wt_t * wt_t);
            float cs  = fminf(nrm, 2.0f) / fmaxf(nrm, 1e-12f);
            float S2  = cs * cs * wtsp2;
            float nn  = sqrtf(S2);
            float ns  = fmaxf(nn, 1e-9f);
            float sh  = sinhf(nn);
            float fac = cs * sh / ns;
            #pragma unroll
            for (int c = 0; c < 4; c++) gam[c] *= fac;
            float sx = sh * nn / ns;
            Ssm = sx * sx;
            tm  = sqrtf(1.f + Ssm);
        }

        #pragma unroll
        for (int it = 0; it < 5; it++) {
            float dl[4];
            #pragma unroll
            for (int c = 0; c < 4; c++) {
                float t = 0.f;
                #pragma unroll
                for (int d = 0; d < 4; d++) t = fmaf(gam[d], P[d][c], t);
                dl[c] = t;
            }
            float wgv[4];
            float A = 0.f, wv_t = 0.f;
            #pragma unroll
            for (int c = 0; c < 4; c++) {
                float alpha = fmaxf(tm * tP[c] - dl[c], 1.0f + 1e-7f);
                float dist  = acoshf(alpha);
                float ut    = tP[c] - alpha * tm;
                float U2sp  = S[c] - 2.f * alpha * dl[c] + alpha * alpha * Ssm;
                float un2   = fmaxf(U2sp - ut * ut, 1e-12f);
                float g     = dist / sqrtf(un2);
                float wg    = wgt[c] * g;
                wgv[c] = wg;
                A    = fmaf(wg, alpha, A);
                wv_t = fmaf(wg, ut, wv_t);
            }
            float wvg[4];
            #pragma unroll
            for (int c = 0; c < 4; c++) wvg[c] = wgv[c] - A * gam[c];

            float wvsp2;
            {
                float t = 0.f;
                #pragma unroll
                for (int c = 0; c < 4; c++) {
                    float u = 0.f;
                    #pragma unroll
                    for (int d = 0; d < 4; d++) u = fmaf(wvg[d], P[c][d], u);
                    t = fmaf(wvg[c], u, t);
                }
                wvsp2 = fmaxf(t, 0.f);
            }

            float nrm = sqrtf(wvsp2 + wv_t * wv_t);
            float cs  = fminf(nrm, 2.0f) / fmaxf(nrm, 1e-12f);
            float q   = 0.1f * cs;
            float mk  = fmaxf(q * q * (wvsp2 - wv_t * wv_t), 1e-12f);
            float th  = sqrtf(mk);
            float ch  = coshf(th);
            float shh = sinhf(th);
            float cq  = shh * q / th;

            #pragma unroll
            for (int c = 0; c < 4; c++) gam[c] = fmaf(cq, wvg[c], ch * gam[c]);

            {
                float t = 0.f;
                #pragma unroll
                for (int c = 0; c < 4; c++) {
                    float u = 0.f;
                    #pragma unroll
                    for (int d = 0; d < 4; d++) u = fmaf(gam[d], P[c][d], u);
                    t = fmaf(gam[c], u, t);
                }
                Ssm = fmaxf(t, 0.f);
            }
            tm = sqrtf(1.f + Ssm);
        }

        if (l < 16) {
            #pragma unroll
            for (int c = 0; c < 4; c++) gout[row * 8 + c] = gam[c];
            gout[row * 8 + 4] = tm;
        }
    }
    __syncthreads();

    // -------- Phase C: re-load h (L1-hot), combine, streaming store --------
    #pragma unroll
    for (int t = 0; t < 2; t++) {
        const int lr = 2 * w + t;
        const int r  = blockIdx.x * RPB + lr;

        float g0 = gout[lr * 8 + 0], g1 = gout[lr * 8 + 1];
        float g2 = gout[lr * 8 + 2], g3 = gout[lr * 8 + 3];
        float tm = gout[lr * 8 + 4];

        const float* h0 = out + 0 * ((size_t)ROWS * DIM) + (size_t)r * DIM + 1;
        const float* h1 = out + 1 * ((size_t)ROWS * DIM) + (size_t)r * DIM + 1;
        const float* h2 = out + 2 * ((size_t)ROWS * DIM) + (size_t)r * DIM + 1;
        const float* h3 = out + 3 * ((size_t)ROWS * DIM) + (size_t)r * DIM + 1;
        float* cp = out + 4 * ((size_t)ROWS * DIM) + (size_t)r * DIM;

        #pragma unroll
        for (int j = 0; j < 8; j++) {
            int e = l + 32 * j;
            float vv = g0 * h0[e];
            vv = fmaf(g1, h1[e], vv);
            vv = fmaf(g2, h2[e], vv);
            vv = fmaf(g3, h3[e], vv);
            __stcs(cp + 1 + e, vv);
        }
        if (l == 0) __stcs(cp, tm);
    }
}

extern "C" void kernel_launch(void* const* d_in, const int* in_sizes, int n_in,
                              void* d_out, int out_size) {
    (void)in_sizes; (void)n_in; (void)out_size;
    const float* xt = (const float*)d_in[0];
    const float* xc = (const float*)d_in[1];
    const float* xf = (const float*)d_in[2];
    const float* xr = (const float*)d_in[3];
    const float* W0 = (const float*)d_in[4];
    const float* b0 = (const float*)d_in[5];
    const float* W1 = (const float*)d_in[6];
    const float* b1 = (const float*)d_in[7];
    const float* W2 = (const float*)d_in[8];
    const float* b2 = (const float*)d_in[9];
    const float* W3 = (const float*)d_in[10];
    const float* b3 = (const float*)d_in[11];
    const float* es = (const float*)d_in[12];
    const float* lw = (const float*)d_in[13];
    float* out = (float*)d_out;

    int nsm = 148;
    cudaDeviceGetAttribute(&nsm, cudaDevAttrMultiProcessorCount, 0);
    if (nsm <= 0) nsm = 148;

    encode_hyp_kernel<<<12 * nsm, 256>>>(xt, xc, xf, xr,
                                         W0, b0, W1, b1, W2, b2, W3, b3,
                                         es, out);
    fusion_kernel<<<ROWS / RPB, 256>>>(lw, out);
}